// round 15
// baseline (speedup 1.0000x reference)
#include <cuda_runtime.h>
#include <cuda_fp16.h>
#include <mma.h>
using namespace nvcuda;

#define N_NODES 50000
#define NEDGE   800000
#define ETOT    850000
#define C       128
#define H       8
#define NEG_SLOPE 0.2f
#define MTILE   128
#define GEMM_BLOCKS 391      // ceil(50000/128)
#define FILL_BLOCKS 782      // ceil(800000/1024), 4 edges/thread @256 threads
#define LDH     136          // half ldm (272B rows, 16B-aligned)
#define LDF     136          // float ldm for epilogue scratch
#define SMEM_DYN (2 * 128 * LDH * sizeof(__half))   // 69632 B -> 3 CTAs/SM

// ---------------- scratch (zero-initialized at module load) ----------------
__device__ __align__(16) __half g_h16[N_NODES * C];
__device__ __align__(16) float g_acc[N_NODES * C];
__device__ float g_asrc[N_NODES * H];
__device__ float g_adst[N_NODES * H];
__device__ int   g_deg[N_NODES];
__device__ int   g_off[N_NODES];
__device__ int   g_cursor[N_NODES];
__device__ int   g_csrc[ETOT];
__device__ int   g_ecounter;
__device__ float g_colsum[C];
__device__ float g_colsq[C];

// ---------------- K0: all zeroing in one kernel ----------------
__global__ void k_zero_all() {
    int i = blockIdx.x * 256 + threadIdx.x;
    if (i < N_NODES) g_deg[i] = 0;
    if (blockIdx.x == 0) {
        if (threadIdx.x < C) { g_colsum[threadIdx.x] = 0.f; g_colsq[threadIdx.x] = 0.f; }
        if (threadIdx.x == 255) g_ecounter = 0;
    }
}

// ---------------- K1: degree histogram (4 edges/thread; RED, no return) ----------------
__global__ void k_hist(const int* __restrict__ ei) {
    int base = blockIdx.x * 1024 + threadIdx.x;
    #pragma unroll
    for (int r = 0; r < 4; r++) {
        int eid = base + r * 256;
        if (eid < NEDGE) atomicAdd(&g_deg[ei[NEDGE + eid]], 1);
    }
}

// ---------------- K2: offsets + self-loop placement ----------------
__global__ void k_offsets() {
    int i    = blockIdx.x * 256 + threadIdx.x;
    int lane = threadIdx.x & 31;
    int v = (i < N_NODES) ? (g_deg[i] + 1) : 0;
    int incl = v;
    #pragma unroll
    for (int o = 1; o < 32; o <<= 1) {
        int t = __shfl_up_sync(0xffffffffu, incl, o);
        if (lane >= o) incl += t;
    }
    int total = __shfl_sync(0xffffffffu, incl, 31);
    int wbase = 0;
    if (lane == 0) wbase = atomicAdd(&g_ecounter, total);
    wbase = __shfl_sync(0xffffffffu, wbase, 0);
    if (i < N_NODES) {
        int o = wbase + incl - v;
        g_off[i]    = o;
        g_csrc[o]   = i;
        g_cursor[i] = o + 1;
    }
}

// ---------------- K3: fused [tensor-core GEMM + attention epilogue] | [CSR fill] ----------------
// Fill is independent of the GEMM; its blocks backfill SM slots while gemm blocks run.
__global__ void __launch_bounds__(256, 3)
k_gemm_fill(const float* __restrict__ x, const float* __restrict__ W,
            const float* __restrict__ att_src, const float* __restrict__ att_dst,
            const int* __restrict__ ei) {
    extern __shared__ __align__(32) char smem_raw[];
    __half* sA = (__half*)smem_raw;        // x tile  [128][LDH]
    __half* sB = sA + 128 * LDH;           // W       [128][LDH]
    int tid = threadIdx.x;

    if (blockIdx.x >= GEMM_BLOCKS) {
        // ---- CSR fill: 4 independent edges per thread ----
        int base = (blockIdx.x - GEMM_BLOCKS) * 1024 + tid;
        int e0 = base, e1 = base + 256, e2 = base + 512, e3 = base + 768;
        int s0 = 0, s1 = 0, s2 = 0, s3 = 0, d0 = 0, d1 = 0, d2 = 0, d3 = 0;
        if (e0 < NEDGE) { s0 = ei[e0]; d0 = ei[NEDGE + e0]; }
        if (e1 < NEDGE) { s1 = ei[e1]; d1 = ei[NEDGE + e1]; }
        if (e2 < NEDGE) { s2 = ei[e2]; d2 = ei[NEDGE + e2]; }
        if (e3 < NEDGE) { s3 = ei[e3]; d3 = ei[NEDGE + e3]; }
        int p0 = 0, p1 = 0, p2 = 0, p3 = 0;
        if (e0 < NEDGE) p0 = atomicAdd(&g_cursor[d0], 1);
        if (e1 < NEDGE) p1 = atomicAdd(&g_cursor[d1], 1);
        if (e2 < NEDGE) p2 = atomicAdd(&g_cursor[d2], 1);
        if (e3 < NEDGE) p3 = atomicAdd(&g_cursor[d3], 1);
        if (e0 < NEDGE) g_csrc[p0] = s0;
        if (e1 < NEDGE) g_csrc[p1] = s1;
        if (e2 < NEDGE) g_csrc[p2] = s2;
        if (e3 < NEDGE) g_csrc[p3] = s3;
        return;
    }

    int nbase = blockIdx.x * MTILE;
    for (int i = tid; i < 128 * 32; i += 256) {
        int row = i >> 5, c4 = i & 31;
        int gn = nbase + row;
        float4 v = (gn < N_NODES) ? ((const float4*)x)[gn * 32 + c4]
                                  : make_float4(0.f, 0.f, 0.f, 0.f);
        __half2 h0 = __floats2half2_rn(v.x, v.y);
        __half2 h1 = __floats2half2_rn(v.z, v.w);
        uint2 u; u.x = *(unsigned*)&h0; u.y = *(unsigned*)&h1;
        *((uint2*)(sA + row * LDH) + c4) = u;

        float4 wv = ((const float4*)W)[row * 32 + c4];
        __half2 w0 = __floats2half2_rn(wv.x, wv.y);
        __half2 w1 = __floats2half2_rn(wv.z, wv.w);
        uint2 uw; uw.x = *(unsigned*)&w0; uw.y = *(unsigned*)&w1;
        *((uint2*)(sB + row * LDH) + c4) = uw;
    }
    __syncthreads();

    int w = tid >> 5, lane = tid & 31;

    wmma::fragment<wmma::accumulator, 16, 16, 16, float> acc[8];
    #pragma unroll
    for (int nt = 0; nt < 8; nt++) wmma::fill_fragment(acc[nt], 0.f);

    #pragma unroll
    for (int ks = 0; ks < 8; ks++) {
        wmma::fragment<wmma::matrix_a, 16, 16, 16, __half, wmma::row_major> a;
        wmma::load_matrix_sync(a, sA + (w * 16) * LDH + ks * 16, LDH);
        #pragma unroll
        for (int nt = 0; nt < 8; nt++) {
            wmma::fragment<wmma::matrix_b, 16, 16, 16, __half, wmma::row_major> b;
            wmma::load_matrix_sync(b, sB + (ks * 16) * LDH + nt * 16, LDH);
            wmma::mma_sync(acc[nt], a, b, acc[nt]);
        }
    }
    __syncthreads();

    float* sc = (float*)smem_raw + w * (16 * LDF);
    #pragma unroll
    for (int nt = 0; nt < 8; nt++)
        wmma::store_matrix_sync(sc + nt * 16, acc[nt], LDF, wmma::mem_row_major);
    __syncwarp();

    int r = lane >> 1, p = lane & 1;
    int n = nbase + w * 16 + r;
    if (n < N_NODES) {
        const float4* row4 = (const float4*)(sc + r * LDF) + p * 16;
        const float4* as4 = ((const float4*)att_src) + p * 16;
        const float4* ad4 = ((const float4*)att_dst) + p * 16;
        uint4* hout = ((uint4*)(g_h16 + n * C)) + p * 8;
        float ps[4] = {0.f, 0.f, 0.f, 0.f};
        float pd[4] = {0.f, 0.f, 0.f, 0.f};
        #pragma unroll
        for (int q = 0; q < 8; q++) {
            float4 v0 = row4[q * 2], v1 = row4[q * 2 + 1];
            float4 a0 = as4[q * 2], a1 = as4[q * 2 + 1];
            float4 b0 = ad4[q * 2], b1 = ad4[q * 2 + 1];
            int hh = q >> 1;
            ps[hh] += v0.x*a0.x + v0.y*a0.y + v0.z*a0.z + v0.w*a0.w
                    + v1.x*a1.x + v1.y*a1.y + v1.z*a1.z + v1.w*a1.w;
            pd[hh] += v0.x*b0.x + v0.y*b0.y + v0.z*b0.z + v0.w*b0.w
                    + v1.x*b1.x + v1.y*b1.y + v1.z*b1.z + v1.w*b1.w;
            __half2 q0 = __floats2half2_rn(v0.x, v0.y);
            __half2 q1 = __floats2half2_rn(v0.z, v0.w);
            __half2 q2 = __floats2half2_rn(v1.x, v1.y);
            __half2 q3 = __floats2half2_rn(v1.z, v1.w);
            uint4 u;
            u.x = *(unsigned*)&q0; u.y = *(unsigned*)&q1;
            u.z = *(unsigned*)&q2; u.w = *(unsigned*)&q3;
            hout[q] = u;
        }
        #pragma unroll
        for (int i2 = 0; i2 < 4; i2++) {
            g_asrc[n * H + p * 4 + i2] = ps[i2];
            g_adst[n * H + p * 4 + i2] = pd[i2];
        }
    }
}

// ---------------- K4: warp-per-dst aggregate; lane-specialized exp; atomic-free BN reduce ----------------
__global__ void k_aggregate() {
    __shared__ float sred[8][C];   // per-warp acc slabs, 4KB
    int t = threadIdx.x;
    int warp = blockIdx.x * 8 + (t >> 5);
    int w    = t >> 5;
    int lane = t & 31;
    int hd   = lane >> 2;      // accumulation head (4 lanes/head)
    int eL   = lane >> 3;      // exp role: edge 0..3
    int hL   = lane & 7;       // exp role: head

    float den = 0.f;
    float4 acc = make_float4(0.f, 0.f, 0.f, 0.f);

    if (warp < N_NODES) {
        int beg = g_off[warp];
        int end = beg + g_deg[warp] + 1;
        float adstL  = g_adst[warp * H + hL];
        float adstHd = g_adst[warp * H + hd];
        const uint2* h16 = (const uint2*)g_h16;

        for (int bp = beg; bp < end; bp += 32) {
            int myp = bp + lane;
            int sv = (myp < end) ? g_csrc[myp] : 0;
            int cnt = min(32, end - bp);
            int j = 0;
            for (; j + 4 <= cnt; j += 4) {
                int se = __shfl_sync(0xffffffffu, sv, j + eL);
                float ev = g_asrc[se * H + hL];
                int s0 = __shfl_sync(0xffffffffu, sv, j);
                int s1 = __shfl_sync(0xffffffffu, sv, j + 1);
                int s2 = __shfl_sync(0xffffffffu, sv, j + 2);
                int s3 = __shfl_sync(0xffffffffu, sv, j + 3);
                uint2 u0 = h16[s0 * 32 + lane];
                uint2 u1 = h16[s1 * 32 + lane];
                uint2 u2 = h16[s2 * 32 + lane];
                uint2 u3 = h16[s3 * 32 + lane];
                ev += adstL;
                ev = (ev > 0.f) ? ev : NEG_SLOPE * ev;
                float xv = __expf(ev);
                float x0 = __shfl_sync(0xffffffffu, xv, hd);
                float x1 = __shfl_sync(0xffffffffu, xv, 8 + hd);
                float x2 = __shfl_sync(0xffffffffu, xv, 16 + hd);
                float x3 = __shfl_sync(0xffffffffu, xv, 24 + hd);
                den += (x0 + x1) + (x2 + x3);
                float2 l0 = __half22float2(*(__half2*)&u0.x), m0 = __half22float2(*(__half2*)&u0.y);
                float2 l1 = __half22float2(*(__half2*)&u1.x), m1 = __half22float2(*(__half2*)&u1.y);
                float2 l2 = __half22float2(*(__half2*)&u2.x), m2 = __half22float2(*(__half2*)&u2.y);
                float2 l3 = __half22float2(*(__half2*)&u3.x), m3 = __half22float2(*(__half2*)&u3.y);
                acc.x += x0 * l0.x; acc.y += x0 * l0.y; acc.z += x0 * m0.x; acc.w += x0 * m0.y;
                acc.x += x1 * l1.x; acc.y += x1 * l1.y; acc.z += x1 * m1.x; acc.w += x1 * m1.y;
                acc.x += x2 * l2.x; acc.y += x2 * l2.y; acc.z += x2 * m2.x; acc.w += x2 * m2.y;
                acc.x += x3 * l3.x; acc.y += x3 * l3.y; acc.z += x3 * m3.x; acc.w += x3 * m3.y;
            }
            for (; j < cnt; j++) {
                int s = __shfl_sync(0xffffffffu, sv, j);
                float e = g_asrc[s * H + hd] + adstHd;
                e = (e > 0.f) ? e : NEG_SLOPE * e;
                float ex = __expf(e);
                den += ex;
                uint2 u = h16[s * 32 + lane];
                float2 lo = __half22float2(*(__half2*)&u.x);
                float2 hi = __half22float2(*(__half2*)&u.y);
                acc.x += ex * lo.x; acc.y += ex * lo.y;
                acc.z += ex * hi.x; acc.w += ex * hi.y;
            }
        }

        float inv = 1.f / (den + 1e-16f);
        acc.x *= inv; acc.y *= inv; acc.z *= inv; acc.w *= inv;
        ((float4*)g_acc)[warp * 32 + lane] = acc;
    } else {
        acc = make_float4(0.f, 0.f, 0.f, 0.f);
    }

    *(float4*)&sred[w][lane * 4] = acc;
    __syncthreads();
    if (t < C) {
        float s = 0.f, q = 0.f;
        #pragma unroll
        for (int w2 = 0; w2 < 8; w2++) {
            float v = sred[w2][t];
            s += v;
            q += v * v;
        }
        atomicAdd(&g_colsum[t], s);
        atomicAdd(&g_colsq[t], q);
    }
}

// ---------------- K5: normalize + ReLU ----------------
__global__ void k_final(const float* __restrict__ gamma, const float* __restrict__ beta,
                        float* __restrict__ out) {
    __shared__ float sscale[C];
    __shared__ float sshift[C];
    int t = threadIdx.x;
    if (t < C) {
        float inv_n = 1.f / (float)N_NODES;
        float mean = g_colsum[t] * inv_n;
        float var  = g_colsq[t] * inv_n - mean * mean;
        float sc   = gamma[t] * rsqrtf(var + 1e-5f);
        sscale[t] = sc;
        sshift[t] = beta[t] - mean * sc;
    }
    __syncthreads();
    int v4 = blockIdx.x * 256 + t;
    if (v4 < N_NODES * 32) {
        int cb = (v4 & 31) * 4;
        float4 a = ((const float4*)g_acc)[v4];
        float4 r;
        r.x = fmaxf(a.x * sscale[cb + 0] + sshift[cb + 0], 0.f);
        r.y = fmaxf(a.y * sscale[cb + 1] + sshift[cb + 1], 0.f);
        r.z = fmaxf(a.z * sscale[cb + 2] + sshift[cb + 2], 0.f);
        r.w = fmaxf(a.w * sscale[cb + 3] + sshift[cb + 3], 0.f);
        ((float4*)out)[v4] = r;
    }
}

// ---------------- launch ----------------
extern "C" void kernel_launch(void* const* d_in, const int* in_sizes, int n_in,
                              void* d_out, int out_size) {
    const float* x       = (const float*)d_in[0];
    const int*   ei      = (const int*)d_in[1];
    const float* W       = (const float*)d_in[2];
    const float* att_src = (const float*)d_in[3];
    const float* att_dst = (const float*)d_in[4];
    const float* gamma   = (const float*)d_in[6];
    const float* beta    = (const float*)d_in[7];
    float*       out     = (float*)d_out;

    cudaFuncSetAttribute(k_gemm_fill, cudaFuncAttributeMaxDynamicSharedMemorySize, (int)SMEM_DYN);

    k_zero_all<<<(N_NODES + 255) / 256, 256>>>();
    k_hist<<<FILL_BLOCKS, 256>>>(ei);
    k_offsets<<<(N_NODES + 255) / 256, 256>>>();
    k_gemm_fill<<<GEMM_BLOCKS + FILL_BLOCKS, 256, SMEM_DYN>>>(x, W, att_src, att_dst, ei);  // profiled (index 3)
    k_aggregate<<<(N_NODES + 7) / 8, 256>>>();
    k_final<<<(N_NODES * 32 + 255) / 256, 256>>>(gamma, beta, out);
}

// round 16
// speedup vs baseline: 1.0204x; 1.0204x over previous
#include <cuda_runtime.h>
#include <cuda_fp16.h>
#include <mma.h>
using namespace nvcuda;

#define N_NODES 50000
#define NEDGE   800000
#define ETOT    850000
#define C       128
#define H       8
#define NEG_SLOPE 0.2f
#define MTILE   128
#define GEMM_BLOCKS 391      // ceil(50000/128)
#define HIST_BLOCKS 782      // ceil(800000/1024), 4 edges/thread @256 threads
#define FILL_BLOCKS 782
#define LDH     136          // half ldm (272B rows, 16B-aligned)
#define LDF     136          // float ldm for epilogue scratch
#define SMEM_DYN (2 * 128 * LDH * sizeof(__half))   // 69632 B -> 3 CTAs/SM

// ---------------- scratch (zero-initialized at module load; kernels restore zeros) ----------------
__device__ __align__(16) __half g_h16[N_NODES * C];
__device__ __align__(16) float g_acc[N_NODES * C];
__device__ float g_asrc[N_NODES * H];
__device__ float g_adst[N_NODES * H];
__device__ int   g_deg[N_NODES];
__device__ int   g_off[N_NODES];
__device__ int   g_cursor[N_NODES];
__device__ int   g_csrc[ETOT];
__device__ int   g_ecounter;
__device__ float g_colsum[C];
__device__ float g_colsq[C];

// ---------------- K1: fused [tensor-core GEMM + attention epilogue] | [degree histogram] ----------------
__global__ void __launch_bounds__(256, 3)
k_gemm_hist(const float* __restrict__ x, const float* __restrict__ W,
            const float* __restrict__ att_src, const float* __restrict__ att_dst,
            const int* __restrict__ ei) {
    extern __shared__ __align__(32) char smem_raw[];
    __half* sA = (__half*)smem_raw;        // x tile  [128][LDH]
    __half* sB = sA + 128 * LDH;           // W       [128][LDH]
    int tid = threadIdx.x;

    if (blockIdx.x >= GEMM_BLOCKS) {
        int base = (blockIdx.x - GEMM_BLOCKS) * 1024 + tid;
        #pragma unroll
        for (int r = 0; r < 4; r++) {
            int eid = base + r * 256;
            if (eid < NEDGE) atomicAdd(&g_deg[ei[NEDGE + eid]], 1);
        }
        return;
    }

    int nbase = blockIdx.x * MTILE;
    for (int i = tid; i < 128 * 32; i += 256) {
        int row = i >> 5, c4 = i & 31;
        int gn = nbase + row;
        float4 v = (gn < N_NODES) ? ((const float4*)x)[gn * 32 + c4]
                                  : make_float4(0.f, 0.f, 0.f, 0.f);
        __half2 h0 = __floats2half2_rn(v.x, v.y);
        __half2 h1 = __floats2half2_rn(v.z, v.w);
        uint2 u; u.x = *(unsigned*)&h0; u.y = *(unsigned*)&h1;
        *((uint2*)(sA + row * LDH) + c4) = u;

        float4 wv = ((const float4*)W)[row * 32 + c4];
        __half2 w0 = __floats2half2_rn(wv.x, wv.y);
        __half2 w1 = __floats2half2_rn(wv.z, wv.w);
        uint2 uw; uw.x = *(unsigned*)&w0; uw.y = *(unsigned*)&w1;
        *((uint2*)(sB + row * LDH) + c4) = uw;
    }
    __syncthreads();

    int w = tid >> 5, lane = tid & 31;

    wmma::fragment<wmma::accumulator, 16, 16, 16, float> acc[8];
    #pragma unroll
    for (int nt = 0; nt < 8; nt++) wmma::fill_fragment(acc[nt], 0.f);

    #pragma unroll
    for (int ks = 0; ks < 8; ks++) {
        wmma::fragment<wmma::matrix_a, 16, 16, 16, __half, wmma::row_major> a;
        wmma::load_matrix_sync(a, sA + (w * 16) * LDH + ks * 16, LDH);
        #pragma unroll
        for (int nt = 0; nt < 8; nt++) {
            wmma::fragment<wmma::matrix_b, 16, 16, 16, __half, wmma::row_major> b;
            wmma::load_matrix_sync(b, sB + (ks * 16) * LDH + nt * 16, LDH);
            wmma::mma_sync(acc[nt], a, b, acc[nt]);
        }
    }
    __syncthreads();

    float* sc = (float*)smem_raw + w * (16 * LDF);
    #pragma unroll
    for (int nt = 0; nt < 8; nt++)
        wmma::store_matrix_sync(sc + nt * 16, acc[nt], LDF, wmma::mem_row_major);
    __syncwarp();

    int r = lane >> 1, p = lane & 1;
    int n = nbase + w * 16 + r;
    if (n < N_NODES) {
        const float4* row4 = (const float4*)(sc + r * LDF) + p * 16;
        const float4* as4 = ((const float4*)att_src) + p * 16;
        const float4* ad4 = ((const float4*)att_dst) + p * 16;
        uint4* hout = ((uint4*)(g_h16 + n * C)) + p * 8;
        float ps[4] = {0.f, 0.f, 0.f, 0.f};
        float pd[4] = {0.f, 0.f, 0.f, 0.f};
        #pragma unroll
        for (int q = 0; q < 8; q++) {
            float4 v0 = row4[q * 2], v1 = row4[q * 2 + 1];
            float4 a0 = as4[q * 2], a1 = as4[q * 2 + 1];
            float4 b0 = ad4[q * 2], b1 = ad4[q * 2 + 1];
            int hh = q >> 1;
            ps[hh] += v0.x*a0.x + v0.y*a0.y + v0.z*a0.z + v0.w*a0.w
                    + v1.x*a1.x + v1.y*a1.y + v1.z*a1.z + v1.w*a1.w;
            pd[hh] += v0.x*b0.x + v0.y*b0.y + v0.z*b0.z + v0.w*b0.w
                    + v1.x*b1.x + v1.y*b1.y + v1.z*b1.z + v1.w*b1.w;
            __half2 q0 = __floats2half2_rn(v0.x, v0.y);
            __half2 q1 = __floats2half2_rn(v0.z, v0.w);
            __half2 q2 = __floats2half2_rn(v1.x, v1.y);
            __half2 q3 = __floats2half2_rn(v1.z, v1.w);
            uint4 u;
            u.x = *(unsigned*)&q0; u.y = *(unsigned*)&q1;
            u.z = *(unsigned*)&q2; u.w = *(unsigned*)&q3;
            hout[q] = u;
        }
        #pragma unroll
        for (int i2 = 0; i2 < 4; i2++) {
            g_asrc[n * H + p * 4 + i2] = ps[i2];
            g_adst[n * H + p * 4 + i2] = pd[i2];
        }
    }
}

// ---------------- K2: offsets + self-loop placement ----------------
__global__ void k_offsets() {
    int i    = blockIdx.x * 256 + threadIdx.x;
    int lane = threadIdx.x & 31;
    int v = (i < N_NODES) ? (g_deg[i] + 1) : 0;
    int incl = v;
    #pragma unroll
    for (int o = 1; o < 32; o <<= 1) {
        int t = __shfl_up_sync(0xffffffffu, incl, o);
        if (lane >= o) incl += t;
    }
    int total = __shfl_sync(0xffffffffu, incl, 31);
    int wbase = 0;
    if (lane == 0) wbase = atomicAdd(&g_ecounter, total);
    wbase = __shfl_sync(0xffffffffu, wbase, 0);
    if (i < N_NODES) {
        int o = wbase + incl - v;
        g_off[i]    = o;
        g_csrc[o]   = i;
        g_cursor[i] = o + 1;
    }
}

// ---------------- K3: fill CSR (4 edges/thread) + stats/counter reset ----------------
__global__ void k_fill(const int* __restrict__ ei) {
    if (blockIdx.x == 0) {   // reset for this call's aggregate / next call's offsets
        if (threadIdx.x < C) { g_colsum[threadIdx.x] = 0.f; g_colsq[threadIdx.x] = 0.f; }
        if (threadIdx.x == 255) g_ecounter = 0;
    }
    int base = blockIdx.x * 1024 + threadIdx.x;
    int e0 = base, e1 = base + 256, e2 = base + 512, e3 = base + 768;
    int s0 = 0, s1 = 0, s2 = 0, s3 = 0, d0 = 0, d1 = 0, d2 = 0, d3 = 0;
    if (e0 < NEDGE) { s0 = ei[e0]; d0 = ei[NEDGE + e0]; }
    if (e1 < NEDGE) { s1 = ei[e1]; d1 = ei[NEDGE + e1]; }
    if (e2 < NEDGE) { s2 = ei[e2]; d2 = ei[NEDGE + e2]; }
    if (e3 < NEDGE) { s3 = ei[e3]; d3 = ei[NEDGE + e3]; }
    int p0 = 0, p1 = 0, p2 = 0, p3 = 0;
    if (e0 < NEDGE) p0 = atomicAdd(&g_cursor[d0], 1);
    if (e1 < NEDGE) p1 = atomicAdd(&g_cursor[d1], 1);
    if (e2 < NEDGE) p2 = atomicAdd(&g_cursor[d2], 1);
    if (e3 < NEDGE) p3 = atomicAdd(&g_cursor[d3], 1);
    if (e0 < NEDGE) g_csrc[p0] = s0;
    if (e1 < NEDGE) g_csrc[p1] = s1;
    if (e2 < NEDGE) g_csrc[p2] = s2;
    if (e3 < NEDGE) g_csrc[p3] = s3;
}

// ---------------- K4: warp-per-dst aggregate; lane-specialized exp; atomic-free BN reduce ----------------
__global__ void k_aggregate() {
    __shared__ float sred[8][C];
    int t = threadIdx.x;
    int warp = blockIdx.x * 8 + (t >> 5);
    int w    = t >> 5;
    int lane = t & 31;
    int hd   = lane >> 2;
    int eL   = lane >> 3;
    int hL   = lane & 7;

    float den = 0.f;
    float4 acc = make_float4(0.f, 0.f, 0.f, 0.f);

    if (warp < N_NODES) {
        int beg = g_off[warp];
        int end = beg + g_deg[warp] + 1;
        float adstL  = g_adst[warp * H + hL];
        float adstHd = g_adst[warp * H + hd];
        const uint2* h16 = (const uint2*)g_h16;

        for (int bp = beg; bp < end; bp += 32) {
            int myp = bp + lane;
            int sv = (myp < end) ? g_csrc[myp] : 0;
            int cnt = min(32, end - bp);
            int j = 0;
            for (; j + 4 <= cnt; j += 4) {
                int se = __shfl_sync(0xffffffffu, sv, j + eL);
                float ev = g_asrc[se * H + hL];
                int s0 = __shfl_sync(0xffffffffu, sv, j);
                int s1 = __shfl_sync(0xffffffffu, sv, j + 1);
                int s2 = __shfl_sync(0xffffffffu, sv, j + 2);
                int s3 = __shfl_sync(0xffffffffu, sv, j + 3);
                uint2 u0 = h16[s0 * 32 + lane];
                uint2 u1 = h16[s1 * 32 + lane];
                uint2 u2 = h16[s2 * 32 + lane];
                uint2 u3 = h16[s3 * 32 + lane];
                ev += adstL;
                ev = (ev > 0.f) ? ev : NEG_SLOPE * ev;
                float xv = __expf(ev);
                float x0 = __shfl_sync(0xffffffffu, xv, hd);
                float x1 = __shfl_sync(0xffffffffu, xv, 8 + hd);
                float x2 = __shfl_sync(0xffffffffu, xv, 16 + hd);
                float x3 = __shfl_sync(0xffffffffu, xv, 24 + hd);
                den += (x0 + x1) + (x2 + x3);
                float2 l0 = __half22float2(*(__half2*)&u0.x), m0 = __half22float2(*(__half2*)&u0.y);
                float2 l1 = __half22float2(*(__half2*)&u1.x), m1 = __half22float2(*(__half2*)&u1.y);
                float2 l2 = __half22float2(*(__half2*)&u2.x), m2 = __half22float2(*(__half2*)&u2.y);
                float2 l3 = __half22float2(*(__half2*)&u3.x), m3 = __half22float2(*(__half2*)&u3.y);
                acc.x += x0 * l0.x; acc.y += x0 * l0.y; acc.z += x0 * m0.x; acc.w += x0 * m0.y;
                acc.x += x1 * l1.x; acc.y += x1 * l1.y; acc.z += x1 * m1.x; acc.w += x1 * m1.y;
                acc.x += x2 * l2.x; acc.y += x2 * l2.y; acc.z += x2 * m2.x; acc.w += x2 * m2.y;
                acc.x += x3 * l3.x; acc.y += x3 * l3.y; acc.z += x3 * m3.x; acc.w += x3 * m3.y;
            }
            for (; j < cnt; j++) {
                int s = __shfl_sync(0xffffffffu, sv, j);
                float e = g_asrc[s * H + hd] + adstHd;
                e = (e > 0.f) ? e : NEG_SLOPE * e;
                float ex = __expf(e);
                den += ex;
                uint2 u = h16[s * 32 + lane];
                float2 lo = __half22float2(*(__half2*)&u.x);
                float2 hi = __half22float2(*(__half2*)&u.y);
                acc.x += ex * lo.x; acc.y += ex * lo.y;
                acc.z += ex * hi.x; acc.w += ex * hi.y;
            }
        }

        float inv = 1.f / (den + 1e-16f);
        acc.x *= inv; acc.y *= inv; acc.z *= inv; acc.w *= inv;
        ((float4*)g_acc)[warp * 32 + lane] = acc;
    } else {
        acc = make_float4(0.f, 0.f, 0.f, 0.f);
    }

    *(float4*)&sred[w][lane * 4] = acc;
    __syncthreads();
    if (t < C) {
        float s = 0.f, q = 0.f;
        #pragma unroll
        for (int w2 = 0; w2 < 8; w2++) {
            float v = sred[w2][t];
            s += v;
            q += v * v;
        }
        atomicAdd(&g_colsum[t], s);
        atomicAdd(&g_colsq[t], q);
    }
}

// ---------------- K5: normalize + ReLU (+ deg reset for next invocation) ----------------
__global__ void k_final(const float* __restrict__ gamma, const float* __restrict__ beta,
                        float* __restrict__ out) {
    __shared__ float sscale[C];
    __shared__ float sshift[C];
    int t = threadIdx.x;
    if (t < C) {
        float inv_n = 1.f / (float)N_NODES;
        float mean = g_colsum[t] * inv_n;
        float var  = g_colsq[t] * inv_n - mean * mean;
        float sc   = gamma[t] * rsqrtf(var + 1e-5f);
        sscale[t] = sc;
        sshift[t] = beta[t] - mean * sc;
    }
    __syncthreads();
    int v4 = blockIdx.x * 256 + t;
    if (v4 < N_NODES) g_deg[v4] = 0;   // deg dead after aggregate; restore zero
    if (v4 < N_NODES * 32) {
        int cb = (v4 & 31) * 4;
        float4 a = ((const float4*)g_acc)[v4];
        float4 r;
        r.x = fmaxf(a.x * sscale[cb + 0] + sshift[cb + 0], 0.f);
        r.y = fmaxf(a.y * sscale[cb + 1] + sshift[cb + 1], 0.f);
        r.z = fmaxf(a.z * sscale[cb + 2] + sshift[cb + 2], 0.f);
        r.w = fmaxf(a.w * sscale[cb + 3] + sshift[cb + 3], 0.f);
        ((float4*)out)[v4] = r;
    }
}

// ---------------- launch ----------------
extern "C" void kernel_launch(void* const* d_in, const int* in_sizes, int n_in,
                              void* d_out, int out_size) {
    const float* x       = (const float*)d_in[0];
    const int*   ei      = (const int*)d_in[1];
    const float* W       = (const float*)d_in[2];
    const float* att_src = (const float*)d_in[3];
    const float* att_dst = (const float*)d_in[4];
    const float* gamma   = (const float*)d_in[6];
    const float* beta    = (const float*)d_in[7];
    float*       out     = (float*)d_out;

    cudaFuncSetAttribute(k_gemm_hist, cudaFuncAttributeMaxDynamicSharedMemorySize, (int)SMEM_DYN);

    k_gemm_hist<<<GEMM_BLOCKS + HIST_BLOCKS, 256, SMEM_DYN>>>(x, W, att_src, att_dst, ei);
    k_offsets<<<(N_NODES + 255) / 256, 256>>>();
    k_fill<<<FILL_BLOCKS, 256>>>(ei);
    k_aggregate<<<(N_NODES + 7) / 8, 256>>>();              // profiled (index 3)
    k_final<<<(N_NODES * 32 + 255) / 256, 256>>>(gamma, beta, out);
}